// round 11
// baseline (speedup 1.0000x reference)
#include <cuda_runtime.h>
#include <cstdint>

// AdEx neuron scan, T=2048, N=32768. spikes[t,n] in f32 {0,1}.
// w == 0 identically (A=0, B=0, w0=0) -> dropped.
// Fast path (valid while V <= -20 mV, where 2*exp((V-0.6)/2) < 7e-5 cannot
// affect spiking): V' = 0.995*V + 0.005*(I - 70), spike = 0.
// Rare path: exact per-tile redo (exp + spike/reset) overwriting the zeros.
//
// R11 vs R6 (best) / R7 (regressed): keep R6's cp.async pipeline, but write
// the (scan-independent) zero output for tile i+1 cooperatively with STG.128
// at iteration i -- UNCONDITIONALLY and with NO extra barrier (R7's mistake
// was a second __syncthreads + flag exchange to pick zero-vs-redo). The rare
// exact-redo of tile i overwrites zeros written one iteration earlier; the
// __syncthreads at the top of iteration i orders that write-write pair
// (cta-scope fence), so the redo's values win. Cuts fast-path store issue
// from 2048 STG.32 (10.2k cyc/warp) to 512 STG.128 (6.1k cyc/warp), the
// co-binding LSU resource at R6's 72.8% DRAM.

#define AX_N  32768
#define BLK   64              // threads per block == columns per block
#define RTILE 32              // rows (timesteps) per tile
#define DEPTH 5               // SMEM ring buffers
#define TILE_ELEMS (RTILE * BLK)   // 2048 floats = 8KB

__device__ __forceinline__ void issue_tile(const float* __restrict__ I,
                                           int tile, int slot, int n0, int tid,
                                           float (*buf)[TILE_ELEMS]) {
    const float* gbase = I + (size_t)tile * RTILE * AX_N + n0;
    uint32_t sbase = (uint32_t)__cvta_generic_to_shared(&buf[slot][0]);
    #pragma unroll
    for (int j = 0; j < 8; ++j) {
        const int idx = tid + j * BLK;   // 0..511
        const int r = idx >> 4;          // 0..31
        const int c = idx & 15;          // 0..15
        const float* g = gbase + (size_t)r * AX_N + c * 4;
        const uint32_t s = sbase + (uint32_t)(r * BLK + c * 4) * 4u;
        asm volatile("cp.async.cg.shared.global [%0], [%1], 16;\n"
                     :: "r"(s), "l"(g));
    }
    asm volatile("cp.async.commit_group;\n" ::: "memory");
}

// Cooperatively zero rows [t0, t0+RTILE) x cols [n0, n0+BLK):
// 512 float4, 8 STG.128 per thread, fully coalesced.
__device__ __forceinline__ void zero_tile(float* __restrict__ S, int t0,
                                          int n0, int tid) {
    const float4 z = make_float4(0.f, 0.f, 0.f, 0.f);
    #pragma unroll
    for (int j = 0; j < 8; ++j) {
        const int idx = tid + j * BLK;
        const int row = idx >> 4;          // 0..31
        const int col4 = idx & 15;         // 0..15
        __stcs((float4*)(S + (size_t)(t0 + row) * AX_N + n0) + col4, z);
    }
}

__global__ void __launch_bounds__(BLK, 4)
adex_kernel(const float* __restrict__ I, float* __restrict__ S, int T) {
    __shared__ __align__(128) float buf[DEPTH][TILE_ELEMS];

    const int tid = threadIdx.x;
    const int n0 = blockIdx.x * BLK;
    const int n = n0 + tid;

    float* op = S + n;
    float V = -70.0f;   // E_L

    const int ntiles = T / RTILE;

    // Prologue: DEPTH-1 tiles in flight; zeros for tile 0 written up front.
    for (int p = 0; p < DEPTH - 1 && p < ntiles; ++p)
        issue_tile(I, p, p, n0, tid, buf);
    if (ntiles > 0)
        zero_tile(S, 0, n0, tid);

    for (int i = 0; i < ntiles; ++i) {
        asm volatile("cp.async.wait_group %0;\n" :: "n"(DEPTH - 2) : "memory");
        __syncthreads();   // tile i visible; also orders zeros(i) written at
                           // iter i-1 before any rare-redo stores to tile i.

        if (i + DEPTH - 1 < ntiles)
            issue_tile(I, i + DEPTH - 1, (i + DEPTH - 1) % DEPTH, n0, tid, buf);

        // Zeros for the NEXT tile (scan-independent; rare redo of tile i+1,
        // if any, happens after the next iteration's barrier).
        if (i + 1 < ntiles)
            zero_tile(S, (i + 1) * RTILE, n0, tid);

        const float* tb = buf[i % DEPTH];
        const int t0 = i * RTILE;

        // Scan (registers only, no stores on the fast path).
        const float Vs = V;
        float v = V;
        float m = V;
        #pragma unroll
        for (int r = 0; r < RTILE; ++r) {
            const float iv = tb[r * BLK + tid];
            v = fmaf(0.995f, v, fmaf(0.005f, iv, -0.35f));
            m = fmaxf(m, v);
        }
        if (__any_sync(0xFFFFFFFFu, m > -20.0f)) {
            // Exact AdEx redo (rare): overwrites this thread's column of the
            // zeros written for tile i at iteration i-1 (ordered by barrier).
            v = Vs;
            #pragma unroll 1
            for (int r = 0; r < RTILE; ++r) {
                const float iv = tb[r * BLK + tid];
                const float e = 2.0f * expf((v - 0.6f) * 0.5f);
                float Vn = v + 0.005f * ((-70.0f - v) + e + iv);
                float s = 0.0f;
                if (Vn >= 30.0f) { s = 1.0f; Vn = -65.0f; }
                v = Vn;
                __stcs(op + (size_t)(t0 + r) * AX_N, s);
            }
        }
        V = v;
    }

    // Scalar tail (T % RTILE != 0): always-exact path, direct global loads.
    for (int t = ntiles * RTILE; t < T; ++t) {
        const float iv = __ldcs(I + (size_t)t * AX_N + n);
        const float e = 2.0f * expf((V - 0.6f) * 0.5f);
        float Vn = V + 0.005f * ((-70.0f - V) + e + iv);
        float s = 0.0f;
        if (Vn >= 30.0f) { s = 1.0f; Vn = -65.0f; }
        V = Vn;
        __stcs(op + (size_t)t * AX_N, s);
    }
}

extern "C" void kernel_launch(void* const* d_in, const int* in_sizes, int n_in,
                              void* d_out, int out_size) {
    const float* I = (const float*)d_in[0];
    float* S = (float*)d_out;
    const int T = in_sizes[0] / AX_N;   // 2048
    adex_kernel<<<AX_N / BLK, BLK>>>(I, S, T);   // 512 blocks x 64 threads
}

// round 12
// speedup vs baseline: 1.1563x; 1.1563x over previous
#include <cuda_runtime.h>
#include <cstdint>

// AdEx neuron scan, T=2048, N=32768. spikes[t,n] in f32 {0,1}.
// w == 0 identically (A=0, B=0, w0=0) -> dropped.
// Fast path (valid while V <= -20 mV, where 2*exp((V-0.6)/2) < 7e-5 cannot
// affect spiking): V' = 0.995*V + 0.005*(I - 70), spike = 0.
// Rare path: exact per-tile redo (exp + spike/reset); same-thread overwrite
// of the fast-path zeros (program-order, no sync needed).
//
// R12 vs R6 (best so far): identical pipeline structure (cp.async SMEM ring,
// interleaved scalar stores in the scan loop -- R7/R11 showed decoupled
// store bursts regress), but fixed GRID GEOMETRY: R6's 512 blocks / 148 SMs
// = 3.46 blocks/SM leaves a 4th-wave tail on 68 SMs (~15% imbalance, which
// exactly explains the 72.8% DRAM plateau: 0.85 * ~6.8TB/s = 5.77TB/s
// measured). Now 1024 one-warp blocks (6.92/SM -> 1.2% imbalance). One warp
// per block also removes __syncthreads entirely (cp.async wait + __syncwarp
// suffices for cross-lane SMEM visibility).

#define AX_N  32768
#define BLK   32              // one warp; threads == columns per block
#define RTILE 32              // rows (timesteps) per tile
#define DEPTH 6               // SMEM ring buffers (5 tiles in flight)
#define TILE_ELEMS (RTILE * BLK)   // 1024 floats = 4KB

__device__ __forceinline__ void issue_tile(const float* __restrict__ I,
                                           int tile, int slot, int n0, int tid,
                                           float (*buf)[TILE_ELEMS]) {
    const float* gbase = I + (size_t)tile * RTILE * AX_N + n0;
    uint32_t sbase = (uint32_t)__cvta_generic_to_shared(&buf[slot][0]);
    // 4KB tile = 256 16B chunks; 8 per lane. Row = 32 floats = 8 chunks.
    #pragma unroll
    for (int j = 0; j < 8; ++j) {
        const int idx = tid + j * BLK;   // 0..255
        const int r = idx >> 3;          // 0..31
        const int c = idx & 7;           // 0..7
        const float* g = gbase + (size_t)r * AX_N + c * 4;
        const uint32_t s = sbase + (uint32_t)(r * BLK + c * 4) * 4u;
        asm volatile("cp.async.cg.shared.global [%0], [%1], 16;\n"
                     :: "r"(s), "l"(g));
    }
    asm volatile("cp.async.commit_group;\n" ::: "memory");
}

__global__ void __launch_bounds__(BLK, 7)
adex_kernel(const float* __restrict__ I, float* __restrict__ S, int T) {
    __shared__ __align__(128) float buf[DEPTH][TILE_ELEMS];

    const int tid = threadIdx.x;           // == lane
    const int n0 = blockIdx.x * BLK;
    const int n = n0 + tid;

    float* op = S + n;
    float V = -70.0f;   // E_L

    const int ntiles = T / RTILE;          // 64 for T=2048

    // Prologue: DEPTH-1 tiles in flight.
    for (int p = 0; p < DEPTH - 1 && p < ntiles; ++p)
        issue_tile(I, p, p, n0, tid, buf);

    for (int i = 0; i < ntiles; ++i) {
        asm volatile("cp.async.wait_group %0;\n" :: "n"(DEPTH - 2) : "memory");
        __syncwarp();   // all lanes past their wait -> tile i fully visible

        if (i + DEPTH - 1 < ntiles)
            issue_tile(I, i + DEPTH - 1, (i + DEPTH - 1) % DEPTH, n0, tid, buf);

        const float* tb = buf[i % DEPTH];
        const int t0 = i * RTILE;

        // Fast path: interleaved LDS + FFMA chain + zero store (proven best
        // structure; stores overlap the dependent FFMA latency).
        const float Vs = V;
        float v = V;
        float m = V;
        #pragma unroll
        for (int r = 0; r < RTILE; ++r) {
            const float iv = tb[r * BLK + tid];
            v = fmaf(0.995f, v, fmaf(0.005f, iv, -0.35f));
            m = fmaxf(m, v);
            __stcs(op + (size_t)(t0 + r) * AX_N, 0.0f);
        }
        if (__any_sync(0xFFFFFFFFu, m > -20.0f)) {
            // Exact AdEx redo (rare): same thread re-stores its own
            // addresses -> program-order supersedes the zeros.
            v = Vs;
            #pragma unroll 1
            for (int r = 0; r < RTILE; ++r) {
                const float iv = tb[r * BLK + tid];
                const float e = 2.0f * expf((v - 0.6f) * 0.5f);
                float Vn = v + 0.005f * ((-70.0f - v) + e + iv);
                float s = 0.0f;
                if (Vn >= 30.0f) { s = 1.0f; Vn = -65.0f; }
                v = Vn;
                __stcs(op + (size_t)(t0 + r) * AX_N, s);
            }
        }
        V = v;
    }

    // Scalar tail (T % RTILE != 0): always-exact path, direct global loads.
    for (int t = ntiles * RTILE; t < T; ++t) {
        const float iv = __ldcs(I + (size_t)t * AX_N + n);
        const float e = 2.0f * expf((V - 0.6f) * 0.5f);
        float Vn = V + 0.005f * ((-70.0f - V) + e + iv);
        float s = 0.0f;
        if (Vn >= 30.0f) { s = 1.0f; Vn = -65.0f; }
        V = Vn;
        __stcs(op + (size_t)t * AX_N, s);
    }
}

extern "C" void kernel_launch(void* const* d_in, const int* in_sizes, int n_in,
                              void* d_out, int out_size) {
    const float* I = (const float*)d_in[0];
    float* S = (float*)d_out;
    const int T = in_sizes[0] / AX_N;   // 2048
    adex_kernel<<<AX_N / BLK, BLK>>>(I, S, T);   // 1024 one-warp blocks
}